// round 2
// baseline (speedup 1.0000x reference)
#include <cuda_runtime.h>

// Problem constants
#define NB   16          // batch
#define TT   255         // teacher length (T-1)
#define UU   1024        // GRU units
#define VV   32000       // vocab
#define EE   256         // emb dim
#define LATD 512         // latent dim
#define MROWS (NB*TT)    // 4080
#define N3   (3*UU)      // 3072

#define GRU_BLOCKS 128
#define GRU_SMEM ((NB*UU + NB*24)*4)

// ---------------- device scratch (no allocs allowed) ----------------
__device__ float g_h[2][NB*UU];                 // ping-pong hidden state
__device__ float g_xproj[(size_t)MROWS*N3];     // x @ gru_kernel + b0   (~50 MB)
__device__ float g_gruout[(size_t)MROWS*UU];    // GRU outputs y         (~16.7 MB)
__device__ int   g_arow[MROWS];                 // gathered token per (b,t)
__device__ unsigned char g_flag[MROWS];         // prefix-OR of mask
__device__ unsigned int g_bar_cnt = 0;
__device__ unsigned int g_bar_gen = 0;

// ---------------- helpers ----------------
__device__ __forceinline__ unsigned long long packdup(float a){
    unsigned long long r;
    asm("mov.b64 %0, {%1, %1};" : "=l"(r) : "f"(a));
    return r;
}
__device__ __forceinline__ void ffma2(float2& c, unsigned long long a2, float2 b){
    unsigned long long b2, c2;
    b2 = *reinterpret_cast<unsigned long long*>(&b);
    c2 = *reinterpret_cast<unsigned long long*>(&c);
    asm("fma.rn.f32x2 %0, %1, %2, %3;" : "=l"(c2) : "l"(a2), "l"(b2), "l"(c2));
    c = *reinterpret_cast<float2*>(&c2);
}

__device__ __forceinline__ void grid_barrier(){
    __syncthreads();
    if (threadIdx.x == 0){
        __threadfence();
        unsigned gen = *(volatile unsigned*)&g_bar_gen;
        if (atomicAdd(&g_bar_cnt, 1) == gridDim.x - 1){
            g_bar_cnt = 0;
            __threadfence();
            atomicAdd(&g_bar_gen, 1);
        } else {
            while (*(volatile unsigned*)&g_bar_gen == gen) { __nanosleep(64); }
            __threadfence();
        }
    }
    __syncthreads();
}

// ---------------- kernel 1: h0 = latent @ dense_W + dense_b ----------------
__global__ void h0_kernel(const float* __restrict__ lat,
                          const float* __restrict__ W,
                          const float* __restrict__ bb){
    int o = blockIdx.x*blockDim.x + threadIdx.x;
    if (o >= NB*UU) return;
    int b = o >> 10, u = o & (UU-1);
    float acc = bb[u];
    const float* lrow = lat + b*LATD;
    #pragma unroll 8
    for (int k=0;k<LATD;k++) acc = fmaf(lrow[k], W[(size_t)k*UU + u], acc);
    g_h[0][o] = acc;
}

// ---------------- kernel 2: per-(b,t) token index + prefix-OR mask flag ----------------
// tokens arrive as int32 (harness downcasts int64 inputs)
__global__ void prep_kernel(const int* __restrict__ tok){
    int tid = threadIdx.x;
    if (tid < NB){
        unsigned char f = 0;
        for (int t=0;t<TT;t++){
            f |= (tok[tid*256 + t] != 0) ? 1 : 0;
            g_flag[tid*TT + t] = f;
        }
    }
    for (int m=tid; m<MROWS; m+=blockDim.x){
        int v = tok[(m/TT)*256 + (m%TT)];
        if (v < 0) v = 0;
        if (v >= VV) v = VV-1;
        g_arow[m] = v;
    }
}

// ---------------- kernel 3: tiled f32x2 GEMM  C[M,N] = gather(A)[M,K] @ B[K,N] + bias ----------------
// tiles: 128x128, K-chunk 8, 256 threads, 8x8 micro-tile per thread, packed fma.rn.f32x2
template<bool GATHER>
__global__ __launch_bounds__(256) void gemm128(
    const float* __restrict__ A, int lda,
    const float* __restrict__ B, int ldb,
    const float* __restrict__ bias,
    float* __restrict__ C, int ldc,
    int M, int K,
    const int* __restrict__ arow)
{
    __shared__ __align__(16) float As[2][8][128];
    __shared__ __align__(16) float Bs[2][8][128];
    const int tid = threadIdx.x;
    const int tx = tid & 15, ty = tid >> 4;
    const int n0 = blockIdx.x * 128;
    const int m0 = blockIdx.y * 128;

    const int lrow = tid & 127, lkq = tid >> 7;        // A loader: 128 rows x 2 k-quads
    const int lncol = (tid & 31) * 4, lkr = tid >> 5;  // B loader: 8 k-rows x 32 n-quads

    float2 acc[8][4];
    #pragma unroll
    for (int i=0;i<8;i++)
        #pragma unroll
        for (int p=0;p<4;p++) acc[i][p] = make_float2(0.f,0.f);

    auto fetchA = [&](int k0)->float4{
        int m = m0 + lrow;
        if (m >= M) return make_float4(0.f,0.f,0.f,0.f);
        const float* base = GATHER ? (A + (size_t)arow[m]*lda) : (A + (size_t)m*lda);
        return *(const float4*)(base + k0 + lkq*4);
    };
    auto fetchB = [&](int k0)->float4{
        return *(const float4*)(B + (size_t)(k0+lkr)*ldb + n0 + lncol);
    };

    {   float4 a = fetchA(0), b = fetchB(0);
        As[0][lkq*4+0][lrow]=a.x; As[0][lkq*4+1][lrow]=a.y;
        As[0][lkq*4+2][lrow]=a.z; As[0][lkq*4+3][lrow]=a.w;
        *(float4*)&Bs[0][lkr][lncol] = b;
    }
    __syncthreads();

    int buf = 0;
    for (int k0=0;k0<K;k0+=8){
        float4 na, nb;
        const bool more = (k0+8) < K;
        if (more){ na = fetchA(k0+8); nb = fetchB(k0+8); }
        #pragma unroll
        for (int kk=0;kk<8;kk++){
            float4 a0 = *(const float4*)&As[buf][kk][ty*4];
            float4 a1 = *(const float4*)&As[buf][kk][64+ty*4];
            float4 b0 = *(const float4*)&Bs[buf][kk][tx*4];
            float4 b1 = *(const float4*)&Bs[buf][kk][64+tx*4];
            float av[8] = {a0.x,a0.y,a0.z,a0.w,a1.x,a1.y,a1.z,a1.w};
            float2 bp[4] = {make_float2(b0.x,b0.y),make_float2(b0.z,b0.w),
                            make_float2(b1.x,b1.y),make_float2(b1.z,b1.w)};
            #pragma unroll
            for (int i=0;i<8;i++){
                unsigned long long ap = packdup(av[i]);
                #pragma unroll
                for (int p=0;p<4;p++) ffma2(acc[i][p], ap, bp[p]);
            }
        }
        if (more){
            As[buf^1][lkq*4+0][lrow]=na.x; As[buf^1][lkq*4+1][lrow]=na.y;
            As[buf^1][lkq*4+2][lrow]=na.z; As[buf^1][lkq*4+3][lrow]=na.w;
            *(float4*)&Bs[buf^1][lkr][lncol] = nb;
        }
        __syncthreads();
        buf ^= 1;
    }

    #pragma unroll
    for (int i=0;i<8;i++){
        int ri = m0 + (i<4 ? ty*4+i : 64 + ty*4 + (i-4));
        if (ri < M){
            #pragma unroll
            for (int p=0;p<4;p++){
                int cj = n0 + (p<2 ? tx*4 + 2*p : 64 + tx*4 + 2*(p-2));
                float2 bb = *(const float2*)(bias + cj);
                float2 v = make_float2(acc[i][p].x + bb.x, acc[i][p].y + bb.y);
                *(float2*)(C + (size_t)ri*ldc + cj) = v;
            }
        }
    }
}

// ---------------- kernel 4: persistent GRU ----------------
// 128 co-resident blocks (<=148 SMs), block bl owns units [bl*8, bl*8+8).
// Recurrent weights live in registers (96 floats/thread) for all 255 steps.
// h broadcast each step via global ping-pong + one software grid barrier/step.
__global__ __launch_bounds__(256,1) void gru_kernel(
    const float* __restrict__ rk,     // gru_rkernel (1024, 3072)
    const float* __restrict__ gbias,  // gru_bias (2, 3072)
    const int* __restrict__ tok)
{
    extern __shared__ float sh[];
    float* h_sh  = sh;                 // 16*1024 floats
    float* rp_sh = sh + NB*UU;         // 16*24 floats
    const int tid = threadIdx.x, lane = tid & 31, wrp = tid >> 5, bl = blockIdx.x;

    // persistent recurrent weights: warp wrp owns local cols {3w,3w+1,3w+2} of 24
    float w0[32], w1[32], w2[32];
    {
        int c0 = wrp*3, c1 = c0+1, c2 = c0+2;
        int g0 = (c0>>3)*UU + bl*8 + (c0&7);
        int g1 = (c1>>3)*UU + bl*8 + (c1&7);
        int g2 = (c2>>3)*UU + bl*8 + (c2&7);
        #pragma unroll
        for (int i=0;i<32;i++){
            int k = i*32 + lane;       // strided k ownership -> conflict-free LDS
            w0[i] = rk[(size_t)k*N3 + g0];
            w1[i] = rk[(size_t)k*N3 + g1];
            w2[i] = rk[(size_t)k*N3 + g2];
        }
    }

    int eb=0, eu=0, ecol=0;
    float bz=0.f, br=0.f, bh=0.f;
    if (tid < 128){
        eb = tid >> 3; eu = tid & 7; ecol = bl*8 + eu;
        bz = gbias[N3 + ecol];
        br = gbias[N3 + UU + ecol];
        bh = gbias[N3 + 2*UU + ecol];
    }

    for (int t=0; t<TT; t++){
        const int rbuf = t & 1, wbuf = rbuf ^ 1;

        // prefetch epilogue inputs early (hide L2 latency under rp compute)
        float xz=0.f, xr=0.f, xh=0.f; bool msk=false, fl=false;
        if (tid < 128){
            int r = eb*TT + t;
            const float* xp = g_xproj + (size_t)r*N3;
            xz = xp[ecol]; xr = xp[UU+ecol]; xh = xp[2*UU+ecol];
            msk = (tok[eb*256 + t] != 0);
            fl  = (g_flag[r] != 0);
        }

        // broadcast h into shared
        {
            const float4* src = (const float4*)g_h[rbuf];
            float4* dst = (float4*)h_sh;
            #pragma unroll 4
            for (int i=tid; i<NB*UU/4; i+=256) dst[i] = src[i];
        }
        __syncthreads();

        // rp = h @ rkernel (this block's 24 columns, all 16 batches)
        for (int b=0;b<NB;b++){
            float a0=0.f,a1=0.f,a2=0.f;
            const float* hb = h_sh + b*UU;
            #pragma unroll
            for (int i=0;i<32;i++){
                float hv = hb[i*32 + lane];
                a0 = fmaf(hv,w0[i],a0);
                a1 = fmaf(hv,w1[i],a1);
                a2 = fmaf(hv,w2[i],a2);
            }
            #pragma unroll
            for (int o=16;o>0;o>>=1){
                a0 += __shfl_xor_sync(0xffffffffu, a0, o);
                a1 += __shfl_xor_sync(0xffffffffu, a1, o);
                a2 += __shfl_xor_sync(0xffffffffu, a2, o);
            }
            if (lane==0){
                rp_sh[b*24 + wrp*3 + 0] = a0;
                rp_sh[b*24 + wrp*3 + 1] = a1;
                rp_sh[b*24 + wrp*3 + 2] = a2;
            }
        }
        __syncthreads();

        // gate math + state update (one thread per (b, unit))
        if (tid < 128){
            float rz = rp_sh[eb*24 + eu]      + bz;
            float rr = rp_sh[eb*24 + 8 + eu]  + br;
            float rh = rp_sh[eb*24 + 16 + eu] + bh;
            float z  = 1.f/(1.f + __expf(-(xz+rz)));
            float rg = 1.f/(1.f + __expf(-(xr+rr)));
            float hh = tanhf(xh + rg*rh);
            float hold = h_sh[eb*UU + ecol];
            float hn = z*hold + (1.f - z)*hh;
            float hnew = msk ? hn : hold;
            g_h[wbuf][eb*UU + ecol] = hnew;
            g_gruout[(size_t)(eb*TT + t)*UU + ecol] = fl ? hnew : 0.f;
        }
        grid_barrier();
    }
}

// ---------------- launch ----------------
extern "C" void kernel_launch(void* const* d_in, const int* in_sizes, int n_in,
                              void* d_out, int out_size)
{
    const float* latent = (const float*)d_in[0];
    const int*   tok    = (const int*)d_in[1];     // int64 in reference -> int32 in harness
    const float* emb    = (const float*)d_in[2];
    const float* dW     = (const float*)d_in[3];
    const float* db     = (const float*)d_in[4];
    const float* gk     = (const float*)d_in[5];
    const float* grk    = (const float*)d_in[6];
    const float* gb     = (const float*)d_in[7];
    const float* oW     = (const float*)d_in[8];
    const float* ob     = (const float*)d_in[9];
    float* out = (float*)d_out;

    (void)in_sizes; (void)n_in; (void)out_size;

    cudaFuncSetAttribute(gru_kernel, cudaFuncAttributeMaxDynamicSharedMemorySize, GRU_SMEM);

    void *xproj_p = nullptr, *gruout_p = nullptr, *arow_p = nullptr;
    cudaGetSymbolAddress(&xproj_p,  g_xproj);
    cudaGetSymbolAddress(&gruout_p, g_gruout);
    cudaGetSymbolAddress(&arow_p,   g_arow);

    // 1) h0 and per-(b,t) metadata
    h0_kernel<<<(NB*UU + 255)/256, 256>>>(latent, dW, db);
    prep_kernel<<<1, 256>>>(tok);

    // 2) x_proj = emb[teacher] @ gru_kernel + bias0   (4080 x 3072, K=256)
    gemm128<true><<<dim3(N3/128, (MROWS+127)/128), 256>>>(
        emb, EE, gk, N3, gb, (float*)xproj_p, N3, MROWS, EE, (const int*)arow_p);

    // 3) persistent GRU over 255 steps
    gru_kernel<<<GRU_BLOCKS, 256, GRU_SMEM>>>(grk, gb, tok);

    // 4) logits = gru_out @ out_W + out_b   (4080 x 32000, K=1024)
    gemm128<false><<<dim3(VV/128, (MROWS+127)/128), 256>>>(
        (const float*)gruout_p, UU, oW, VV, ob, out, VV, MROWS, UU, nullptr);
}

// round 4
// speedup vs baseline: 2.1806x; 2.1806x over previous
#include <cuda_runtime.h>
#include <cuda_fp16.h>
#include <cstdint>

// Problem constants
#define NB   16          // batch
#define TT   255         // teacher length (T-1)
#define UU   1024        // GRU units
#define VV   32000       // vocab
#define EE   256         // emb dim
#define LATD 512         // latent dim
#define MROWS (NB*TT)    // 4080
#define MPAD 4096
#define N3   (3*UU)      // 3072

#define GRU_BLOCKS 128
#define GRU_SMEM ((NB*UU + NB*24)*4)

// ---------------- device scratch (no allocs allowed) ----------------
__device__ float g_h[2][NB*UU];                       // ping-pong hidden state
__device__ float g_xproj[(size_t)MROWS*N3];           // x @ gru_kernel + b0
__device__ __align__(128) __half g_Ah[(size_t)MPAD*UU];   // fp16 GRU outputs (rows>=4080 stay 0)
__device__ __align__(128) __half g_Wh[(size_t)VV*UU];     // fp16 out_W^T  [V][U]
__device__ int   g_arow[MROWS];
__device__ unsigned char g_flag[MROWS];
__device__ unsigned int g_bar_cnt = 0;
__device__ unsigned int g_bar_gen = 0;

// ---------------- PTX helpers ----------------
__device__ __forceinline__ uint32_t smem_to_u32(const void* p){
    uint32_t a;
    asm("{ .reg .u64 t; cvta.to.shared.u64 t, %1; cvt.u32.u64 %0, t; }" : "=r"(a) : "l"(p));
    return a;
}
__device__ __forceinline__ void cp16(uint32_t s, const void* g){
    asm volatile("cp.async.cg.shared.global [%0], [%1], 16;" :: "r"(s), "l"(g));
}
__device__ __forceinline__ void cp_commit(){ asm volatile("cp.async.commit_group;" ::: "memory"); }
template<int N> __device__ __forceinline__ void cp_wait(){
    asm volatile("cp.async.wait_group %0;" :: "n"(N) : "memory");
}
__device__ __forceinline__ void ldsm4(uint32_t* r, uint32_t addr){
    asm volatile("ldmatrix.sync.aligned.m8n8.x4.shared.b16 {%0,%1,%2,%3}, [%4];"
        : "=r"(r[0]),"=r"(r[1]),"=r"(r[2]),"=r"(r[3]) : "r"(addr));
}
__device__ __forceinline__ void mma16816(float* c, const uint32_t* a, const uint32_t* b){
    asm volatile("mma.sync.aligned.m16n8k16.row.col.f32.f16.f16.f32 "
        "{%0,%1,%2,%3}, {%4,%5,%6,%7}, {%8,%9}, {%0,%1,%2,%3};"
        : "+f"(c[0]), "+f"(c[1]), "+f"(c[2]), "+f"(c[3])
        : "r"(a[0]), "r"(a[1]), "r"(a[2]), "r"(a[3]), "r"(b[0]), "r"(b[1]));
}

// ---------------- f32x2 helpers (SIMT xproj GEMM) ----------------
__device__ __forceinline__ unsigned long long packdup(float a){
    unsigned long long r;
    asm("mov.b64 %0, {%1, %1};" : "=l"(r) : "f"(a));
    return r;
}
__device__ __forceinline__ void ffma2(float2& c, unsigned long long a2, float2 b){
    unsigned long long b2, c2;
    b2 = *reinterpret_cast<unsigned long long*>(&b);
    c2 = *reinterpret_cast<unsigned long long*>(&c);
    asm("fma.rn.f32x2 %0, %1, %2, %3;" : "=l"(c2) : "l"(a2), "l"(b2), "l"(c2));
    c = *reinterpret_cast<float2*>(&c2);
}

__device__ __forceinline__ void grid_barrier(){
    __syncthreads();
    if (threadIdx.x == 0){
        __threadfence();
        unsigned gen = *(volatile unsigned*)&g_bar_gen;
        if (atomicAdd(&g_bar_cnt, 1) == gridDim.x - 1){
            g_bar_cnt = 0;
            __threadfence();
            atomicAdd(&g_bar_gen, 1);
        } else {
            while (*(volatile unsigned*)&g_bar_gen == gen) { __nanosleep(64); }
            __threadfence();
        }
    }
    __syncthreads();
}

// ---------------- kernel 1: h0 = latent @ dense_W + dense_b ----------------
__global__ void h0_kernel(const float* __restrict__ lat,
                          const float* __restrict__ W,
                          const float* __restrict__ bb){
    int o = blockIdx.x*blockDim.x + threadIdx.x;
    if (o >= NB*UU) return;
    int b = o >> 10, u = o & (UU-1);
    float acc = bb[u];
    const float* lrow = lat + b*LATD;
    #pragma unroll 8
    for (int k=0;k<LATD;k++) acc = fmaf(lrow[k], W[(size_t)k*UU + u], acc);
    g_h[0][o] = acc;
}

// ---------------- kernel 2: token gather index + prefix-OR flag ----------------
__global__ void prep_kernel(const int* __restrict__ tok){
    int tid = threadIdx.x;
    if (tid < NB){
        unsigned char f = 0;
        for (int t=0;t<TT;t++){
            f |= (tok[tid*256 + t] != 0) ? 1 : 0;
            g_flag[tid*TT + t] = f;
        }
    }
    for (int m=tid; m<MROWS; m+=blockDim.x){
        int v = tok[(m/TT)*256 + (m%TT)];
        if (v < 0) v = 0;
        if (v >= VV) v = VV-1;
        g_arow[m] = v;
    }
}

// ---------------- kernel 2b: transpose out_W [U][V] -> fp16 g_Wh [V][U] ----------------
__global__ void convW_kernel(const float* __restrict__ W){
    __shared__ float tile[32][33];
    int n0 = blockIdx.x*32, k0 = blockIdx.y*32;
    int tx = threadIdx.x, ty = threadIdx.y;   // 32 x 8
    #pragma unroll
    for (int i=ty; i<32; i+=8)
        tile[i][tx] = W[(size_t)(k0+i)*VV + n0+tx];
    __syncthreads();
    #pragma unroll
    for (int i=ty; i<32; i+=8){
        int n = n0 + i, k = k0 + tx;
        g_Wh[(size_t)n*UU + k] = __float2half(tile[tx][i]);
    }
}

// ---------------- kernel 3: SIMT f32x2 GEMM for xproj (gathered A) ----------------
template<bool GATHER>
__global__ __launch_bounds__(256) void gemm128(
    const float* __restrict__ A, int lda,
    const float* __restrict__ B, int ldb,
    const float* __restrict__ bias,
    float* __restrict__ C, int ldc,
    int M, int K,
    const int* __restrict__ arow)
{
    __shared__ __align__(16) float As[2][8][128];
    __shared__ __align__(16) float Bs[2][8][128];
    const int tid = threadIdx.x;
    const int tx = tid & 15, ty = tid >> 4;
    const int n0 = blockIdx.x * 128;
    const int m0 = blockIdx.y * 128;

    const int lrow = tid & 127, lkq = tid >> 7;
    const int lncol = (tid & 31) * 4, lkr = tid >> 5;

    float2 acc[8][4];
    #pragma unroll
    for (int i=0;i<8;i++)
        #pragma unroll
        for (int p=0;p<4;p++) acc[i][p] = make_float2(0.f,0.f);

    auto fetchA = [&](int k0)->float4{
        int m = m0 + lrow;
        if (m >= M) return make_float4(0.f,0.f,0.f,0.f);
        const float* base = GATHER ? (A + (size_t)arow[m]*lda) : (A + (size_t)m*lda);
        return *(const float4*)(base + k0 + lkq*4);
    };
    auto fetchB = [&](int k0)->float4{
        return *(const float4*)(B + (size_t)(k0+lkr)*ldb + n0 + lncol);
    };

    {   float4 a = fetchA(0), b = fetchB(0);
        As[0][lkq*4+0][lrow]=a.x; As[0][lkq*4+1][lrow]=a.y;
        As[0][lkq*4+2][lrow]=a.z; As[0][lkq*4+3][lrow]=a.w;
        *(float4*)&Bs[0][lkr][lncol] = b;
    }
    __syncthreads();

    int buf = 0;
    for (int k0=0;k0<K;k0+=8){
        float4 na, nb;
        const bool more = (k0+8) < K;
        if (more){ na = fetchA(k0+8); nb = fetchB(k0+8); }
        #pragma unroll
        for (int kk=0;kk<8;kk++){
            float4 a0 = *(const float4*)&As[buf][kk][ty*4];
            float4 a1 = *(const float4*)&As[buf][kk][64+ty*4];
            float4 b0 = *(const float4*)&Bs[buf][kk][tx*4];
            float4 b1 = *(const float4*)&Bs[buf][kk][64+tx*4];
            float av[8] = {a0.x,a0.y,a0.z,a0.w,a1.x,a1.y,a1.z,a1.w};
            float2 bp[4] = {make_float2(b0.x,b0.y),make_float2(b0.z,b0.w),
                            make_float2(b1.x,b1.y),make_float2(b1.z,b1.w)};
            #pragma unroll
            for (int i=0;i<8;i++){
                unsigned long long ap = packdup(av[i]);
                #pragma unroll
                for (int p=0;p<4;p++) ffma2(acc[i][p], ap, bp[p]);
            }
        }
        if (more){
            As[buf^1][lkq*4+0][lrow]=na.x; As[buf^1][lkq*4+1][lrow]=na.y;
            As[buf^1][lkq*4+2][lrow]=na.z; As[buf^1][lkq*4+3][lrow]=na.w;
            *(float4*)&Bs[buf^1][lkr][lncol] = nb;
        }
        __syncthreads();
        buf ^= 1;
    }

    #pragma unroll
    for (int i=0;i<8;i++){
        int ri = m0 + (i<4 ? ty*4+i : 64 + ty*4 + (i-4));
        if (ri < M){
            #pragma unroll
            for (int p=0;p<4;p++){
                int cj = n0 + (p<2 ? tx*4 + 2*p : 64 + tx*4 + 2*(p-2));
                float2 bb = *(const float2*)(bias + cj);
                float2 v = make_float2(acc[i][p].x + bb.x, acc[i][p].y + bb.y);
                *(float2*)(C + (size_t)ri*ldc + cj) = v;
            }
        }
    }
}

// ---------------- kernel 4: persistent GRU (writes fp16 A directly) ----------------
__global__ __launch_bounds__(256,1) void gru_kernel(
    const float* __restrict__ rk,
    const float* __restrict__ gbias,
    const int* __restrict__ tok)
{
    extern __shared__ float sh[];
    float* h_sh  = sh;
    float* rp_sh = sh + NB*UU;
    const int tid = threadIdx.x, lane = tid & 31, wrp = tid >> 5, bl = blockIdx.x;

    float w0[32], w1[32], w2[32];
    {
        int c0 = wrp*3, c1 = c0+1, c2 = c0+2;
        int g0 = (c0>>3)*UU + bl*8 + (c0&7);
        int g1 = (c1>>3)*UU + bl*8 + (c1&7);
        int g2 = (c2>>3)*UU + bl*8 + (c2&7);
        #pragma unroll
        for (int i=0;i<32;i++){
            int k = i*32 + lane;
            w0[i] = rk[(size_t)k*N3 + g0];
            w1[i] = rk[(size_t)k*N3 + g1];
            w2[i] = rk[(size_t)k*N3 + g2];
        }
    }

    int eb=0, eu=0, ecol=0;
    float bz=0.f, br=0.f, bh=0.f;
    if (tid < 128){
        eb = tid >> 3; eu = tid & 7; ecol = bl*8 + eu;
        bz = gbias[N3 + ecol];
        br = gbias[N3 + UU + ecol];
        bh = gbias[N3 + 2*UU + ecol];
    }

    for (int t=0; t<TT; t++){
        const int rbuf = t & 1, wbuf = rbuf ^ 1;

        float xz=0.f, xr=0.f, xh=0.f; bool msk=false, fl=false;
        if (tid < 128){
            int r = eb*TT + t;
            const float* xp = g_xproj + (size_t)r*N3;
            xz = xp[ecol]; xr = xp[UU+ecol]; xh = xp[2*UU+ecol];
            msk = (tok[eb*256 + t] != 0);
            fl  = (g_flag[r] != 0);
        }

        {
            const float4* src = (const float4*)g_h[rbuf];
            float4* dst = (float4*)h_sh;
            #pragma unroll 4
            for (int i=tid; i<NB*UU/4; i+=256) dst[i] = src[i];
        }
        __syncthreads();

        for (int b=0;b<NB;b++){
            float a0=0.f,a1=0.f,a2=0.f;
            const float* hb = h_sh + b*UU;
            #pragma unroll
            for (int i=0;i<32;i++){
                float hv = hb[i*32 + lane];
                a0 = fmaf(hv,w0[i],a0);
                a1 = fmaf(hv,w1[i],a1);
                a2 = fmaf(hv,w2[i],a2);
            }
            #pragma unroll
            for (int o=16;o>0;o>>=1){
                a0 += __shfl_xor_sync(0xffffffffu, a0, o);
                a1 += __shfl_xor_sync(0xffffffffu, a1, o);
                a2 += __shfl_xor_sync(0xffffffffu, a2, o);
            }
            if (lane==0){
                rp_sh[b*24 + wrp*3 + 0] = a0;
                rp_sh[b*24 + wrp*3 + 1] = a1;
                rp_sh[b*24 + wrp*3 + 2] = a2;
            }
        }
        __syncthreads();

        if (tid < 128){
            float rz = rp_sh[eb*24 + eu]      + bz;
            float rr = rp_sh[eb*24 + 8 + eu]  + br;
            float rh = rp_sh[eb*24 + 16 + eu] + bh;
            float z  = 1.f/(1.f + __expf(-(xz+rz)));
            float rg = 1.f/(1.f + __expf(-(xr+rr)));
            float hh = tanhf(xh + rg*rh);
            float hold = h_sh[eb*UU + ecol];
            float hn = z*hold + (1.f - z)*hh;
            float hnew = msk ? hn : hold;
            g_h[wbuf][eb*UU + ecol] = hnew;
            float yv = fl ? hnew : 0.f;
            g_Ah[(size_t)(eb*TT + t)*UU + ecol] = __float2half(yv);
        }
        grid_barrier();
    }
}

// ---------------- kernel 5: fp16 HMMA output GEMM ----------------
// C[4080,32000] = A[4096,1024]h @ W^T[32000,1024]h + bias, fp32 accumulate.
// CTA tile 128x128, K-chunk 64, double-buffered cp.async, 8 warps (2m x 4n),
// warp tile 64x32, ldmatrix + mma.m16n8k16. SMEM rows padded to 72 halves (144B).
#define HG_STRIDE 72
#define HG_BUFB   (128*HG_STRIDE*2)       // 18432 bytes per buffer
#define HG_SMEM   (4*HG_BUFB)             // A0,A1,B0,B1 = 73728

__global__ __launch_bounds__(256,1) void out_hmma(const float* __restrict__ ob,
                                                  float* __restrict__ C){
    extern __shared__ __align__(128) char sm[];
    const uint32_t sb = smem_to_u32(sm);
    const int tid = threadIdx.x, lane = tid & 31, wid = tid >> 5;
    const int m0 = blockIdx.x * 128;
    const int n0 = blockIdx.y * 128;
    const int wm = wid >> 2, wn = wid & 3;     // 2 x 4 warps

    // loader mapping: 1024 cp16 per buffer per operand -> 4 per thread
    const int lr = tid >> 2, ls = tid & 3;     // row 0..63? no: idx scheme below

    auto loadA = [&](int kc, int bufb /*byte base*/){
        const __half* gA = g_Ah + (size_t)m0*UU + kc*64;
        #pragma unroll
        for (int i=0;i<4;i++){
            int idx = tid + i*256;             // 0..1023
            int row = idx >> 3, seg = idx & 7; // 128 rows x 8 segs of 8 halves
            cp16(sb + bufb + (uint32_t)(row*HG_STRIDE + seg*8)*2,
                 gA + (size_t)row*UU + seg*8);
        }
    };
    auto loadB = [&](int kc, int bufb){
        const __half* gB = g_Wh + (size_t)n0*UU + kc*64;
        #pragma unroll
        for (int i=0;i<4;i++){
            int idx = tid + i*256;
            int row = idx >> 3, seg = idx & 7;
            cp16(sb + bufb + (uint32_t)(row*HG_STRIDE + seg*8)*2,
                 gB + (size_t)row*UU + seg*8);
        }
    };

    float acc[4][4][4];
    #pragma unroll
    for (int i=0;i<4;i++)
        #pragma unroll
        for (int j=0;j<4;j++)
            #pragma unroll
            for (int p=0;p<4;p++) acc[i][j][p] = 0.f;

    // per-thread ldmatrix base offsets (bytes)
    const int lane15 = lane & 15, laneHi = lane >> 4;
    const uint32_t aOff = (uint32_t)((wm*64 + lane15)*HG_STRIDE + laneHi*8)*2;
    const int nr  = (lane & 7) + ((lane >> 4) << 3);
    const int kc8 = ((lane >> 3) & 1) * 8;
    const uint32_t bOff = (uint32_t)((wn*32 + nr)*HG_STRIDE + kc8)*2;

    loadA(0, 0); loadB(0, 2*HG_BUFB); cp_commit();

    for (int kc=0; kc<16; kc++){
        int buf = kc & 1;
        if (kc+1 < 16){
            loadA(kc+1, (buf^1)*HG_BUFB);
            loadB(kc+1, (2 + (buf^1))*HG_BUFB);
            cp_commit();
            cp_wait<1>();
        } else {
            cp_wait<0>();
        }
        __syncthreads();

        const uint32_t aBase = sb + buf*HG_BUFB + aOff;
        const uint32_t bBase = sb + (2+buf)*HG_BUFB + bOff;
        #pragma unroll
        for (int k16=0; k16<4; k16++){
            uint32_t af[4][4], bf[2][4];
            #pragma unroll
            for (int mi=0; mi<4; mi++)
                ldsm4(af[mi], aBase + (uint32_t)(mi*16*HG_STRIDE + k16*16)*2);
            #pragma unroll
            for (int ni=0; ni<2; ni++)
                ldsm4(bf[ni], bBase + (uint32_t)(ni*16*HG_STRIDE + k16*16)*2);
            #pragma unroll
            for (int mi=0; mi<4; mi++)
                #pragma unroll
                for (int nt=0; nt<4; nt++)
                    mma16816(acc[mi][nt], af[mi], &bf[nt>>1][(nt&1)*2]);
        }
        __syncthreads();
    }

    // epilogue: bias + store (guard rows >= MROWS)
    const int g = lane >> 2, q = lane & 3;
    float2 bias2[4];
    #pragma unroll
    for (int nt=0; nt<4; nt++){
        int col = n0 + wn*32 + nt*8 + q*2;
        bias2[nt] = *(const float2*)(ob + col);
    }
    #pragma unroll
    for (int mi=0; mi<4; mi++){
        int r0 = m0 + wm*64 + mi*16 + g;
        int r1 = r0 + 8;
        #pragma unroll
        for (int nt=0; nt<4; nt++){
            int col = n0 + wn*32 + nt*8 + q*2;
            if (r0 < MROWS){
                float2 v = make_float2(acc[mi][nt][0] + bias2[nt].x,
                                       acc[mi][nt][1] + bias2[nt].y);
                *(float2*)(C + (size_t)r0*VV + col) = v;
            }
            if (r1 < MROWS){
                float2 v = make_float2(acc[mi][nt][2] + bias2[nt].x,
                                       acc[mi][nt][3] + bias2[nt].y);
                *(float2*)(C + (size_t)r1*VV + col) = v;
            }
        }
    }
}

// ---------------- launch ----------------
extern "C" void kernel_launch(void* const* d_in, const int* in_sizes, int n_in,
                              void* d_out, int out_size)
{
    const float* latent = (const float*)d_in[0];
    const int*   tok    = (const int*)d_in[1];
    const float* emb    = (const float*)d_in[2];
    const float* dW     = (const float*)d_in[3];
    const float* db     = (const float*)d_in[4];
    const float* gk     = (const float*)d_in[5];
    const float* grk    = (const float*)d_in[6];
    const float* gb     = (const float*)d_in[7];
    const float* oW     = (const float*)d_in[8];
    const float* ob     = (const float*)d_in[9];
    float* out = (float*)d_out;

    (void)in_sizes; (void)n_in; (void)out_size;

    cudaFuncSetAttribute(gru_kernel, cudaFuncAttributeMaxDynamicSharedMemorySize, GRU_SMEM);
    cudaFuncSetAttribute(out_hmma, cudaFuncAttributeMaxDynamicSharedMemorySize, HG_SMEM);

    void *xproj_p = nullptr, *arow_p = nullptr;
    cudaGetSymbolAddress(&xproj_p, g_xproj);
    cudaGetSymbolAddress(&arow_p,  g_arow);

    h0_kernel<<<(NB*UU + 255)/256, 256>>>(latent, dW, db);
    prep_kernel<<<1, 256>>>(tok);
    convW_kernel<<<dim3(VV/32, UU/32), dim3(32,8)>>>(oW);

    gemm128<true><<<dim3(N3/128, (MROWS+127)/128), 256>>>(
        emb, EE, gk, N3, gb, (float*)xproj_p, N3, MROWS, EE, (const int*)arow_p);

    gru_kernel<<<GRU_BLOCKS, 256, GRU_SMEM>>>(grk, gb, tok);

    // m tiles fastest (blockIdx.x) so co-resident CTAs share the same B panel in L2
    out_hmma<<<dim3(MPAD/128, VV/128), 256, HG_SMEM>>>(ob, out);
}

// round 5
// speedup vs baseline: 2.5803x; 1.1833x over previous
#include <cuda_runtime.h>
#include <cuda_fp16.h>
#include <cstdint>

// Problem constants
#define NB   16          // batch
#define TT   255         // teacher length (T-1)
#define UU   1024        // GRU units
#define VV   32000       // vocab
#define EE   256         // emb dim
#define LATD 512         // latent dim
#define MROWS (NB*TT)    // 4080
#define MPAD 4096
#define N3   (3*UU)      // 3072

#define GRU_BLOCKS 128
#define HSTR 20                              // padded batch stride in h_sh (floats)
#define GRU_SMEM (1024*HSTR*4 + NB*32*4)     // 81920 + 2048

// ---------------- device scratch (no allocs allowed) ----------------
__device__ float g_hT[2][1024*NB];                    // transposed hidden state [unit][batch], ping-pong
__device__ float g_xproj[(size_t)MROWS*N3];           // x @ gru_kernel + b0
__device__ __align__(128) __half g_Ah[(size_t)MPAD*UU];   // fp16 GRU outputs (rows>=4080 stay 0)
__device__ __align__(128) __half g_Wh[(size_t)VV*UU];     // fp16 out_W^T  [V][U]
__device__ int   g_arow[MROWS];
__device__ unsigned char g_flag[MROWS];
__device__ unsigned int g_bar_cnt = 0;
__device__ unsigned int g_bar_gen = 0;

// ---------------- PTX helpers ----------------
__device__ __forceinline__ uint32_t smem_to_u32(const void* p){
    uint32_t a;
    asm("{ .reg .u64 t; cvta.to.shared.u64 t, %1; cvt.u32.u64 %0, t; }" : "=r"(a) : "l"(p));
    return a;
}
__device__ __forceinline__ void cp16(uint32_t s, const void* g){
    asm volatile("cp.async.cg.shared.global [%0], [%1], 16;" :: "r"(s), "l"(g));
}
__device__ __forceinline__ void cp_commit(){ asm volatile("cp.async.commit_group;" ::: "memory"); }
template<int N> __device__ __forceinline__ void cp_wait(){
    asm volatile("cp.async.wait_group %0;" :: "n"(N) : "memory");
}
__device__ __forceinline__ void ldsm4(uint32_t* r, uint32_t addr){
    asm volatile("ldmatrix.sync.aligned.m8n8.x4.shared.b16 {%0,%1,%2,%3}, [%4];"
        : "=r"(r[0]),"=r"(r[1]),"=r"(r[2]),"=r"(r[3]) : "r"(addr));
}
__device__ __forceinline__ void mma16816(float* c, const uint32_t* a, const uint32_t* b){
    asm volatile("mma.sync.aligned.m16n8k16.row.col.f32.f16.f16.f32 "
        "{%0,%1,%2,%3}, {%4,%5,%6,%7}, {%8,%9}, {%0,%1,%2,%3};"
        : "+f"(c[0]), "+f"(c[1]), "+f"(c[2]), "+f"(c[3])
        : "r"(a[0]), "r"(a[1]), "r"(a[2]), "r"(a[3]), "r"(b[0]), "r"(b[1]));
}

// ---------------- f32x2 helpers ----------------
__device__ __forceinline__ unsigned long long packdup(float a){
    unsigned long long r;
    asm("mov.b64 %0, {%1, %1};" : "=l"(r) : "f"(a));
    return r;
}
__device__ __forceinline__ void ffma2(float2& c, unsigned long long a2, float2 b){
    unsigned long long b2, c2;
    b2 = *reinterpret_cast<unsigned long long*>(&b);
    c2 = *reinterpret_cast<unsigned long long*>(&c);
    asm("fma.rn.f32x2 %0, %1, %2, %3;" : "=l"(c2) : "l"(a2), "l"(b2), "l"(c2));
    c = *reinterpret_cast<float2*>(&c2);
}

// fast grid barrier: acq_rel atomics, pure acquire spin
__device__ __forceinline__ void grid_barrier(){
    __syncthreads();
    if (threadIdx.x == 0){
        unsigned gen, old;
        asm volatile("ld.acquire.gpu.u32 %0, [%1];" : "=r"(gen) : "l"(&g_bar_gen));
        asm volatile("atom.acq_rel.gpu.add.u32 %0, [%1], 1;" : "=r"(old) : "l"(&g_bar_cnt));
        if (old == gridDim.x - 1){
            *(volatile unsigned*)&g_bar_cnt = 0;
            asm volatile("red.release.gpu.add.u32 [%0], 1;" :: "l"(&g_bar_gen));
        } else {
            unsigned g2;
            do {
                asm volatile("ld.acquire.gpu.u32 %0, [%1];" : "=r"(g2) : "l"(&g_bar_gen));
            } while (g2 == gen);
        }
    }
    __syncthreads();
}

// ---------------- kernel 1: h0 = latent @ dense_W + dense_b (writes transposed) ----------------
__global__ void h0_kernel(const float* __restrict__ lat,
                          const float* __restrict__ W,
                          const float* __restrict__ bb){
    int o = blockIdx.x*blockDim.x + threadIdx.x;
    if (o >= NB*UU) return;
    int b = o >> 10, u = o & (UU-1);
    float acc = bb[u];
    const float* lrow = lat + b*LATD;
    #pragma unroll 8
    for (int k=0;k<LATD;k++) acc = fmaf(lrow[k], W[(size_t)k*UU + u], acc);
    g_hT[0][u*NB + b] = acc;
}

// ---------------- kernel 2: token gather index + prefix-OR flag ----------------
__global__ void prep_kernel(const int* __restrict__ tok){
    int tid = threadIdx.x;
    if (tid < NB){
        unsigned char f = 0;
        for (int t=0;t<TT;t++){
            f |= (tok[tid*256 + t] != 0) ? 1 : 0;
            g_flag[tid*TT + t] = f;
        }
    }
    for (int m=tid; m<MROWS; m+=blockDim.x){
        int v = tok[(m/TT)*256 + (m%TT)];
        if (v < 0) v = 0;
        if (v >= VV) v = VV-1;
        g_arow[m] = v;
    }
}

// ---------------- kernel 2b: transpose out_W [U][V] -> fp16 g_Wh [V][U] ----------------
__global__ void convW_kernel(const float* __restrict__ W){
    __shared__ float tile[32][33];
    int n0 = blockIdx.x*32, k0 = blockIdx.y*32;
    int tx = threadIdx.x, ty = threadIdx.y;   // 32 x 8
    #pragma unroll
    for (int i=ty; i<32; i+=8)
        tile[i][tx] = W[(size_t)(k0+i)*VV + n0+tx];
    __syncthreads();
    #pragma unroll
    for (int i=ty; i<32; i+=8){
        int n = n0 + i, k = k0 + tx;
        g_Wh[(size_t)n*UU + k] = __float2half(tile[tx][i]);
    }
}

// ---------------- kernel 3: SIMT f32x2 GEMM for xproj (gathered A) ----------------
template<bool GATHER>
__global__ __launch_bounds__(256) void gemm128(
    const float* __restrict__ A, int lda,
    const float* __restrict__ B, int ldb,
    const float* __restrict__ bias,
    float* __restrict__ C, int ldc,
    int M, int K,
    const int* __restrict__ arow)
{
    __shared__ __align__(16) float As[2][8][128];
    __shared__ __align__(16) float Bs[2][8][128];
    const int tid = threadIdx.x;
    const int tx = tid & 15, ty = tid >> 4;
    const int n0 = blockIdx.x * 128;
    const int m0 = blockIdx.y * 128;

    const int lrow = tid & 127, lkq = tid >> 7;
    const int lncol = (tid & 31) * 4, lkr = tid >> 5;

    float2 acc[8][4];
    #pragma unroll
    for (int i=0;i<8;i++)
        #pragma unroll
        for (int p=0;p<4;p++) acc[i][p] = make_float2(0.f,0.f);

    auto fetchA = [&](int k0)->float4{
        int m = m0 + lrow;
        if (m >= M) return make_float4(0.f,0.f,0.f,0.f);
        const float* base = GATHER ? (A + (size_t)arow[m]*lda) : (A + (size_t)m*lda);
        return *(const float4*)(base + k0 + lkq*4);
    };
    auto fetchB = [&](int k0)->float4{
        return *(const float4*)(B + (size_t)(k0+lkr)*ldb + n0 + lncol);
    };

    {   float4 a = fetchA(0), b = fetchB(0);
        As[0][lkq*4+0][lrow]=a.x; As[0][lkq*4+1][lrow]=a.y;
        As[0][lkq*4+2][lrow]=a.z; As[0][lkq*4+3][lrow]=a.w;
        *(float4*)&Bs[0][lkr][lncol] = b;
    }
    __syncthreads();

    int buf = 0;
    for (int k0=0;k0<K;k0+=8){
        float4 na, nb;
        const bool more = (k0+8) < K;
        if (more){ na = fetchA(k0+8); nb = fetchB(k0+8); }
        #pragma unroll
        for (int kk=0;kk<8;kk++){
            float4 a0 = *(const float4*)&As[buf][kk][ty*4];
            float4 a1 = *(const float4*)&As[buf][kk][64+ty*4];
            float4 b0 = *(const float4*)&Bs[buf][kk][tx*4];
            float4 b1 = *(const float4*)&Bs[buf][kk][64+tx*4];
            float av[8] = {a0.x,a0.y,a0.z,a0.w,a1.x,a1.y,a1.z,a1.w};
            float2 bp[4] = {make_float2(b0.x,b0.y),make_float2(b0.z,b0.w),
                            make_float2(b1.x,b1.y),make_float2(b1.z,b1.w)};
            #pragma unroll
            for (int i=0;i<8;i++){
                unsigned long long ap = packdup(av[i]);
                #pragma unroll
                for (int p=0;p<4;p++) ffma2(acc[i][p], ap, bp[p]);
            }
        }
        if (more){
            As[buf^1][lkq*4+0][lrow]=na.x; As[buf^1][lkq*4+1][lrow]=na.y;
            As[buf^1][lkq*4+2][lrow]=na.z; As[buf^1][lkq*4+3][lrow]=na.w;
            *(float4*)&Bs[buf^1][lkr][lncol] = nb;
        }
        __syncthreads();
        buf ^= 1;
    }

    #pragma unroll
    for (int i=0;i<8;i++){
        int ri = m0 + (i<4 ? ty*4+i : 64 + ty*4 + (i-4));
        if (ri < M){
            #pragma unroll
            for (int p=0;p<4;p++){
                int cj = n0 + (p<2 ? tx*4 + 2*p : 64 + tx*4 + 2*(p-2));
                float2 bb = *(const float2*)(bias + cj);
                float2 v = make_float2(acc[i][p].x + bb.x, acc[i][p].y + bb.y);
                *(float2*)(C + (size_t)ri*ldc + cj) = v;
            }
        }
    }
}

// ---------------- kernel 4: persistent GRU v2 ----------------
// h transposed [unit][batch]: LDS.128 fetches 4 batches; fma.rn.f32x2 over batch pairs.
__global__ __launch_bounds__(256,1) void gru_kernel(
    const float* __restrict__ rk,
    const float* __restrict__ gbias,
    const int* __restrict__ tok)
{
    extern __shared__ float sh[];
    float* hT    = sh;                 // [1024][HSTR]
    float* rp_sh = sh + 1024*HSTR;     // [b][32] (24 used)
    const int tid = threadIdx.x, lane = tid & 31, wrp = tid >> 5, bl = blockIdx.x;

    // persistent recurrent weights: warp wrp owns local cols {3w,3w+1,3w+2} of 24
    float w0[32], w1[32], w2[32];
    {
        int c0 = wrp*3, c1 = c0+1, c2 = c0+2;
        int g0 = (c0>>3)*UU + bl*8 + (c0&7);
        int g1 = (c1>>3)*UU + bl*8 + (c1&7);
        int g2 = (c2>>3)*UU + bl*8 + (c2&7);
        #pragma unroll
        for (int i=0;i<32;i++){
            int k = i*32 + lane;
            w0[i] = rk[(size_t)k*N3 + g0];
            w1[i] = rk[(size_t)k*N3 + g1];
            w2[i] = rk[(size_t)k*N3 + g2];
        }
    }

    int eb=0, eu=0, ecol=0;
    float bz=0.f, br=0.f, bh=0.f;
    if (tid < 128){
        eb = tid >> 3; eu = tid & 7; ecol = bl*8 + eu;
        bz = gbias[N3 + ecol];
        br = gbias[N3 + UU + ecol];
        bh = gbias[N3 + 2*UU + ecol];
    }

    for (int t=0; t<TT; t++){
        const int rbuf = t & 1, wbuf = rbuf ^ 1;

        // prefetch epilogue inputs (hide L2 latency)
        float xz=0.f, xr=0.f, xh=0.f; bool msk=false, fl=false;
        if (tid < 128){
            int r = eb*TT + t;
            const float* xp = g_xproj + (size_t)r*N3;
            xz = xp[ecol]; xr = xp[UU+ecol]; xh = xp[2*UU+ecol];
            msk = (tok[eb*256 + t] != 0);
            fl  = (g_flag[r] != 0);
        }

        // broadcast transposed h into padded SMEM
        {
            const float4* src = (const float4*)&g_hT[rbuf][0];
            #pragma unroll 4
            for (int i=tid; i<1024*NB/4; i+=256){
                float4 v = src[i];
                int u = i >> 2, g = i & 3;
                *(float4*)&hT[u*HSTR + g*4] = v;
            }
        }
        __syncthreads();

        // rp = h @ rkernel: packed over batch pairs
        float2 acc0[8], acc1[8], acc2[8];
        #pragma unroll
        for (int bp=0;bp<8;bp++){ acc0[bp]=make_float2(0.f,0.f); acc1[bp]=make_float2(0.f,0.f); acc2[bp]=make_float2(0.f,0.f); }

        #pragma unroll
        for (int i=0;i<32;i++){
            int k = i*32 + lane;
            const float4* hk = (const float4*)&hT[k*HSTR];
            float4 ha = hk[0], hb4 = hk[1], hc = hk[2], hd = hk[3];
            float2 hp[8] = {{ha.x,ha.y},{ha.z,ha.w},{hb4.x,hb4.y},{hb4.z,hb4.w},
                            {hc.x,hc.y},{hc.z,hc.w},{hd.x,hd.y},{hd.z,hd.w}};
            unsigned long long p0 = packdup(w0[i]), p1 = packdup(w1[i]), p2 = packdup(w2[i]);
            #pragma unroll
            for (int bp=0;bp<8;bp++){
                ffma2(acc0[bp], p0, hp[bp]);
                ffma2(acc1[bp], p1, hp[bp]);
                ffma2(acc2[bp], p2, hp[bp]);
            }
        }

        // lane reduction + store (24 packed values)
        {
            int c0 = wrp*3;
            #pragma unroll
            for (int bp=0;bp<8;bp++){
                float2 v0 = acc0[bp], v1 = acc1[bp], v2 = acc2[bp];
                #pragma unroll
                for (int o=16;o>0;o>>=1){
                    v0.x += __shfl_xor_sync(0xffffffffu, v0.x, o);
                    v0.y += __shfl_xor_sync(0xffffffffu, v0.y, o);
                    v1.x += __shfl_xor_sync(0xffffffffu, v1.x, o);
                    v1.y += __shfl_xor_sync(0xffffffffu, v1.y, o);
                    v2.x += __shfl_xor_sync(0xffffffffu, v2.x, o);
                    v2.y += __shfl_xor_sync(0xffffffffu, v2.y, o);
                }
                if (lane == 0){
                    int b0 = bp*2, b1 = bp*2+1;
                    rp_sh[b0*32 + c0 + 0] = v0.x;  rp_sh[b1*32 + c0 + 0] = v0.y;
                    rp_sh[b0*32 + c0 + 1] = v1.x;  rp_sh[b1*32 + c0 + 1] = v1.y;
                    rp_sh[b0*32 + c0 + 2] = v2.x;  rp_sh[b1*32 + c0 + 2] = v2.y;
                }
            }
        }
        __syncthreads();

        // gate math + state update (one thread per (b, unit))
        if (tid < 128){
            float rz = rp_sh[eb*32 + eu]      + bz;
            float rr = rp_sh[eb*32 + 8 + eu]  + br;
            float rh = rp_sh[eb*32 + 16 + eu] + bh;
            float z  = 1.f/(1.f + __expf(-(xz+rz)));
            float rg = 1.f/(1.f + __expf(-(xr+rr)));
            float hh = tanhf(xh + rg*rh);
            float hold = hT[ecol*HSTR + eb];
            float hn = z*hold + (1.f - z)*hh;
            float hnew = msk ? hn : hold;
            g_hT[wbuf][ecol*NB + eb] = hnew;
            float yv = fl ? hnew : 0.f;
            g_Ah[(size_t)(eb*TT + t)*UU + ecol] = __float2half(yv);
        }
        grid_barrier();
    }
}

// ---------------- kernel 5: fp16 HMMA output GEMM v2 ----------------
// 3-stage cp.async pipeline, one __syncthreads per chunk, 2 CTAs/SM.
#define HG_STRIDE 72
#define HG_BUFB   (128*HG_STRIDE*2)       // 18432 bytes per buffer
#define HG_SMEM   (6*HG_BUFB)             // A0..A2, B0..B2 = 110592

__global__ __launch_bounds__(256,2) void out_hmma(const float* __restrict__ ob,
                                                  float* __restrict__ C){
    extern __shared__ __align__(128) char sm[];
    const uint32_t sb = smem_to_u32(sm);
    const int tid = threadIdx.x, lane = tid & 31, wid = tid >> 5;
    const int m0 = blockIdx.x * 128;
    const int n0 = blockIdx.y * 128;
    const int wm = wid >> 2, wn = wid & 3;     // 2 x 4 warps

    auto loadA = [&](int kc, int st){
        const __half* gA = g_Ah + (size_t)m0*UU + kc*64;
        uint32_t base = sb + st*HG_BUFB;
        #pragma unroll
        for (int i=0;i<4;i++){
            int idx = tid + i*256;             // 0..1023
            int row = idx >> 3, seg = idx & 7; // 128 rows x 8 segs of 8 halves
            cp16(base + (uint32_t)(row*HG_STRIDE + seg*8)*2,
                 gA + (size_t)row*UU + seg*8);
        }
    };
    auto loadB = [&](int kc, int st){
        const __half* gB = g_Wh + (size_t)n0*UU + kc*64;
        uint32_t base = sb + (3+st)*HG_BUFB;
        #pragma unroll
        for (int i=0;i<4;i++){
            int idx = tid + i*256;
            int row = idx >> 3, seg = idx & 7;
            cp16(base + (uint32_t)(row*HG_STRIDE + seg*8)*2,
                 gB + (size_t)row*UU + seg*8);
        }
    };

    float acc[4][4][4];
    #pragma unroll
    for (int i=0;i<4;i++)
        #pragma unroll
        for (int j=0;j<4;j++)
            #pragma unroll
            for (int p=0;p<4;p++) acc[i][j][p] = 0.f;

    const int lane15 = lane & 15, laneHi = lane >> 4;
    const uint32_t aOff = (uint32_t)((wm*64 + lane15)*HG_STRIDE + laneHi*8)*2;
    const int nr  = (lane & 7) + ((lane >> 4) << 3);
    const int kc8 = ((lane >> 3) & 1) * 8;
    const uint32_t bOff = (uint32_t)((wn*32 + nr)*HG_STRIDE + kc8)*2;

    loadA(0,0); loadB(0,0); cp_commit();
    loadA(1,1); loadB(1,1); cp_commit();

    for (int kc=0; kc<16; kc++){
        int st = kc % 3;
        if (kc < 15) cp_wait<1>(); else cp_wait<0>();
        __syncthreads();
        if (kc + 2 < 16){
            loadA(kc+2, (kc+2)%3);
            loadB(kc+2, (kc+2)%3);
            cp_commit();
        }

        const uint32_t aBase = sb + st*HG_BUFB + aOff;
        const uint32_t bBase = sb + (3+st)*HG_BUFB + bOff;
        #pragma unroll
        for (int k16=0; k16<4; k16++){
            uint32_t af[4][4], bf[2][4];
            #pragma unroll
            for (int mi=0; mi<4; mi++)
                ldsm4(af[mi], aBase + (uint32_t)(mi*16*HG_STRIDE + k16*16)*2);
            #pragma unroll
            for (int ni=0; ni<2; ni++)
                ldsm4(bf[ni], bBase + (uint32_t)(ni*16*HG_STRIDE + k16*16)*2);
            #pragma unroll
            for (int mi=0; mi<4; mi++)
                #pragma unroll
                for (int nt=0; nt<4; nt++)
                    mma16816(acc[mi][nt], af[mi], &bf[nt>>1][(nt&1)*2]);
        }
    }

    // epilogue: bias + store (guard rows >= MROWS)
    const int g = lane >> 2, q = lane & 3;
    float2 bias2[4];
    #pragma unroll
    for (int nt=0; nt<4; nt++){
        int col = n0 + wn*32 + nt*8 + q*2;
        bias2[nt] = *(const float2*)(ob + col);
    }
    #pragma unroll
    for (int mi=0; mi<4; mi++){
        int r0 = m0 + wm*64 + mi*16 + g;
        int r1 = r0 + 8;
        #pragma unroll
        for (int nt=0; nt<4; nt++){
            int col = n0 + wn*32 + nt*8 + q*2;
            if (r0 < MROWS){
                float2 v = make_float2(acc[mi][nt][0] + bias2[nt].x,
                                       acc[mi][nt][1] + bias2[nt].y);
                *(float2*)(C + (size_t)r0*VV + col) = v;
            }
            if (r1 < MROWS){
                float2 v = make_float2(acc[mi][nt][2] + bias2[nt].x,
                                       acc[mi][nt][3] + bias2[nt].y);
                *(float2*)(C + (size_t)r1*VV + col) = v;
            }
        }
    }
}

// ---------------- launch ----------------
extern "C" void kernel_launch(void* const* d_in, const int* in_sizes, int n_in,
                              void* d_out, int out_size)
{
    const float* latent = (const float*)d_in[0];
    const int*   tok    = (const int*)d_in[1];
    const float* emb    = (const float*)d_in[2];
    const float* dW     = (const float*)d_in[3];
    const float* db     = (const float*)d_in[4];
    const float* gk     = (const float*)d_in[5];
    const float* grk    = (const float*)d_in[6];
    const float* gb     = (const float*)d_in[7];
    const float* oW     = (const float*)d_in[8];
    const float* ob     = (const float*)d_in[9];
    float* out = (float*)d_out;

    (void)in_sizes; (void)n_in; (void)out_size;

    cudaFuncSetAttribute(gru_kernel, cudaFuncAttributeMaxDynamicSharedMemorySize, GRU_SMEM);
    cudaFuncSetAttribute(out_hmma, cudaFuncAttributeMaxDynamicSharedMemorySize, HG_SMEM);

    void *xproj_p = nullptr, *arow_p = nullptr;
    cudaGetSymbolAddress(&xproj_p, g_xproj);
    cudaGetSymbolAddress(&arow_p,  g_arow);

    h0_kernel<<<(NB*UU + 255)/256, 256>>>(latent, dW, db);
    prep_kernel<<<1, 256>>>(tok);
    convW_kernel<<<dim3(VV/32, UU/32), dim3(32,8)>>>(oW);

    gemm128<true><<<dim3(N3/128, (MROWS+127)/128), 256>>>(
        emb, EE, gk, N3, gb, (float*)xproj_p, N3, MROWS, EE, (const int*)arow_p);

    gru_kernel<<<GRU_BLOCKS, 256, GRU_SMEM>>>(grk, gb, tok);

    // m tiles fastest (blockIdx.x) so co-resident CTAs share the same B panel in L2
    out_hmma<<<dim3(MPAD/128, VV/128), 256, HG_SMEM>>>(ob, out);
}